// round 7
// baseline (speedup 1.0000x reference)
#include <cuda_runtime.h>
#include <cuda_bf16.h>
#include <cstdint>

#define N_NODES 50000
#define N_EDGES 800000
#define IN_CH   128
#define H_CH    128
#define NCAT    256   // W_l and W_r stacked

// ---------------- device scratch ----------------
__device__ float d_w[NCAT * IN_CH];            // packed [W_l; W_r], row-major [256,128]
__device__ float d_g[N_NODES * NCAT];          // row n: [g_l(128) | g_r(128)]
__device__ int   d_count[N_NODES];
__device__ int   d_start[N_NODES + 1];
__device__ int   d_cursor[N_NODES];
__device__ int   d_src_sorted[N_EDGES];
__device__ float d_env_sorted[N_EDGES];

// ---------------- kernel 1: pack W + zero counts (merged) ----------------
__global__ void prep_kernel(const float* __restrict__ Wl, const float* __restrict__ Wr) {
    int i = blockIdx.x * blockDim.x + threadIdx.x;
    if (i < H_CH * IN_CH) {
        d_w[i] = Wl[i];
        d_w[H_CH * IN_CH + i] = Wr[i];
    }
    if (i < N_NODES) d_count[i] = 0;
}

// ---------------- kernel 2: SGEMM  C[M,256] = q[M,128] @ Wcat^T (R3 proven version) ----------------
#define BM 64
#define BN 64
#define BK 16
#define PAD 68

__global__ __launch_bounds__(256) void gemm_kernel(const float* __restrict__ q) {
    __shared__ float As[BK][PAD];  // As[k][m]
    __shared__ float Bs[BK][PAD];  // Bs[k][n]

    const int block_m = blockIdx.x * BM;
    const int block_n = blockIdx.y * BN;
    const int tid = threadIdx.x;
    const int tn = tid & 15;
    const int tm = tid >> 4;

    const int lrow  = tid >> 2;
    const int lcol4 = (tid & 3) << 2;

    float acc[4][4];
#pragma unroll
    for (int i = 0; i < 4; i++)
#pragma unroll
        for (int j = 0; j < 4; j++) acc[i][j] = 0.f;

#pragma unroll
    for (int k0 = 0; k0 < IN_CH; k0 += BK) {
        float4 av = make_float4(0.f, 0.f, 0.f, 0.f);
        int arow = block_m + lrow;
        if (arow < N_NODES)
            av = *reinterpret_cast<const float4*>(&q[arow * IN_CH + k0 + lcol4]);
        As[lcol4 + 0][lrow] = av.x;
        As[lcol4 + 1][lrow] = av.y;
        As[lcol4 + 2][lrow] = av.z;
        As[lcol4 + 3][lrow] = av.w;
        float4 bv = *reinterpret_cast<const float4*>(&d_w[(block_n + lrow) * IN_CH + k0 + lcol4]);
        Bs[lcol4 + 0][lrow] = bv.x;
        Bs[lcol4 + 1][lrow] = bv.y;
        Bs[lcol4 + 2][lrow] = bv.z;
        Bs[lcol4 + 3][lrow] = bv.w;
        __syncthreads();

#pragma unroll
        for (int kk = 0; kk < BK; kk++) {
            float4 a = *reinterpret_cast<const float4*>(&As[kk][tm << 2]);
            float4 b = *reinterpret_cast<const float4*>(&Bs[kk][tn << 2]);
            float ar[4] = {a.x, a.y, a.z, a.w};
            float br[4] = {b.x, b.y, b.z, b.w};
#pragma unroll
            for (int i = 0; i < 4; i++)
#pragma unroll
                for (int j = 0; j < 4; j++) acc[i][j] += ar[i] * br[j];
        }
        __syncthreads();
    }

#pragma unroll
    for (int i = 0; i < 4; i++) {
        int row = block_m + (tm << 2) + i;
        if (row < N_NODES) {
            float4 o = make_float4(acc[i][0], acc[i][1], acc[i][2], acc[i][3]);
            *reinterpret_cast<float4*>(&d_g[row * NCAT + block_n + (tn << 2)]) = o;
        }
    }
}

// ---------------- kernel 3: histogram of dst (4 edges/thread) ----------------
__global__ void hist_kernel(const int* __restrict__ ei) {
    int t = blockIdx.x * blockDim.x + threadIdx.x;
    int i4 = t * 4;
    if (i4 < N_EDGES) {
        int4 d = *reinterpret_cast<const int4*>(&ei[N_EDGES + i4]);
        atomicAdd(&d_count[d.x], 1);
        atomicAdd(&d_count[d.y], 1);
        atomicAdd(&d_count[d.z], 1);
        atomicAdd(&d_count[d.w], 1);
    }
}

// ---------------- kernel 4: exclusive scan, 8 elems/thread, single block ----------------
#define SCAN_T 1024
#define SCAN_V 8
#define SCAN_CHUNK (SCAN_T * SCAN_V)   // 8192

__global__ __launch_bounds__(SCAN_T) void scan_kernel() {
    __shared__ int wt[32];
    int tid = threadIdx.x;
    int lane = tid & 31;
    int wid = tid >> 5;
    int carry = 0;

    for (int base = 0; base < N_NODES; base += SCAN_CHUNK) {
        int idx0 = base + tid * SCAN_V;
        int v[SCAN_V];
        if (idx0 + SCAN_V <= N_NODES) {
            int4 a = *reinterpret_cast<const int4*>(&d_count[idx0]);
            int4 b = *reinterpret_cast<const int4*>(&d_count[idx0 + 4]);
            v[0] = a.x; v[1] = a.y; v[2] = a.z; v[3] = a.w;
            v[4] = b.x; v[5] = b.y; v[6] = b.z; v[7] = b.w;
        } else {
#pragma unroll
            for (int r = 0; r < SCAN_V; r++)
                v[r] = (idx0 + r < N_NODES) ? d_count[idx0 + r] : 0;
        }
        int p[SCAN_V];
        p[0] = v[0];
#pragma unroll
        for (int r = 1; r < SCAN_V; r++) p[r] = p[r - 1] + v[r];
        int s = p[SCAN_V - 1];

        int ws = s;
#pragma unroll
        for (int off = 1; off < 32; off <<= 1) {
            int y = __shfl_up_sync(0xffffffffu, ws, off);
            if (lane >= off) ws += y;
        }
        if (lane == 31) wt[wid] = ws;
        __syncthreads();
        if (tid < 32) {
            int y = wt[tid];
#pragma unroll
            for (int off = 1; off < 32; off <<= 1) {
                int z = __shfl_up_sync(0xffffffffu, y, off);
                if (tid >= off) y += z;
            }
            wt[tid] = y;
        }
        __syncthreads();
        int thr_base = carry + (wid ? wt[wid - 1] : 0) + ws - s;

        if (idx0 + SCAN_V <= N_NODES) {
            int4 oa = make_int4(thr_base + p[0] - v[0], thr_base + p[1] - v[1],
                                thr_base + p[2] - v[2], thr_base + p[3] - v[3]);
            int4 ob = make_int4(thr_base + p[4] - v[4], thr_base + p[5] - v[5],
                                thr_base + p[6] - v[6], thr_base + p[7] - v[7]);
            *reinterpret_cast<int4*>(&d_start[idx0])      = oa;
            *reinterpret_cast<int4*>(&d_start[idx0 + 4])  = ob;
            *reinterpret_cast<int4*>(&d_cursor[idx0])     = oa;
            *reinterpret_cast<int4*>(&d_cursor[idx0 + 4]) = ob;
        } else {
#pragma unroll
            for (int r = 0; r < SCAN_V; r++) {
                if (idx0 + r < N_NODES) {
                    int e = thr_base + p[r] - v[r];
                    d_start[idx0 + r]  = e;
                    d_cursor[idx0 + r] = e;
                }
            }
        }
        int total = wt[31];
        __syncthreads();
        carry += total;
    }
    if (tid == 0) d_start[N_NODES] = carry;
}

// ---------------- kernel 5: scatter edges (4 edges/thread, bounds-guarded) ----------------
__global__ void scatter_kernel(const int* __restrict__ ei,
                               const float* __restrict__ envelope) {
    int t = blockIdx.x * blockDim.x + threadIdx.x;
    int i4 = t * 4;
    if (i4 < N_EDGES) {
        int4   s = *reinterpret_cast<const int4*>(&ei[i4]);
        int4   d = *reinterpret_cast<const int4*>(&ei[N_EDGES + i4]);
        float4 e = *reinterpret_cast<const float4*>(&envelope[i4]);
        int p0 = atomicAdd(&d_cursor[d.x], 1);
        if ((unsigned)p0 < N_EDGES) { d_src_sorted[p0] = s.x; d_env_sorted[p0] = e.x; }
        int p1 = atomicAdd(&d_cursor[d.y], 1);
        if ((unsigned)p1 < N_EDGES) { d_src_sorted[p1] = s.y; d_env_sorted[p1] = e.y; }
        int p2 = atomicAdd(&d_cursor[d.z], 1);
        if ((unsigned)p2 < N_EDGES) { d_src_sorted[p2] = s.z; d_env_sorted[p2] = e.z; }
        int p3 = atomicAdd(&d_cursor[d.w], 1);
        if ((unsigned)p3 < N_EDGES) { d_src_sorted[p3] = s.w; d_env_sorted[p3] = e.w; }
    }
}

// ---------------- kernel 6: per-node softmax + aggregation (warp/node, 2 edges/iter) ----------------
__global__ __launch_bounds__(256) void out_kernel(const float* __restrict__ attn_w,
                                                  float* __restrict__ out) {
    int warp_id = (blockIdx.x * blockDim.x + threadIdx.x) >> 5;
    if (warp_id >= N_NODES) return;
    int lane = threadIdx.x & 31;
    int n = warp_id;

    float4 gr = *reinterpret_cast<const float4*>(&d_g[n * NCAT + H_CH + (lane << 2)]);
    float4 aw = *reinterpret_cast<const float4*>(&attn_w[lane << 2]);

    float acc0 = 0.f, acc1 = 0.f, acc2 = 0.f, acc3 = 0.f;
    float denom = 0.f;

    // clamped bounds: no-op when scan is correct; guarantees termination otherwise
    int js = d_start[n];
    int je = d_start[n + 1];
    js = (js < 0) ? 0 : js;
    je = (je > N_EDGES) ? N_EDGES : je;
    int j = js;

    for (; j + 1 < je; j += 2) {
        int sA = d_src_sorted[j];
        int sB = d_src_sorted[j + 1];
        float eA = d_env_sorted[j];
        float eB = d_env_sorted[j + 1];
        float4 gA = *reinterpret_cast<const float4*>(&d_g[sA * NCAT + (lane << 2)]);
        float4 gB = *reinterpret_cast<const float4*>(&d_g[sB * NCAT + (lane << 2)]);

        float tA0 = gA.x + gr.x, tA1 = gA.y + gr.y, tA2 = gA.z + gr.z, tA3 = gA.w + gr.w;
        float tB0 = gB.x + gr.x, tB1 = gB.y + gr.y, tB2 = gB.z + gr.z, tB3 = gB.w + gr.w;

        float pA = (tA0 * __frcp_rn(1.f + __expf(-tA0))) * aw.x
                 + (tA1 * __frcp_rn(1.f + __expf(-tA1))) * aw.y
                 + (tA2 * __frcp_rn(1.f + __expf(-tA2))) * aw.z
                 + (tA3 * __frcp_rn(1.f + __expf(-tA3))) * aw.w;
        float pB = (tB0 * __frcp_rn(1.f + __expf(-tB0))) * aw.x
                 + (tB1 * __frcp_rn(1.f + __expf(-tB1))) * aw.y
                 + (tB2 * __frcp_rn(1.f + __expf(-tB2))) * aw.z
                 + (tB3 * __frcp_rn(1.f + __expf(-tB3))) * aw.w;

#pragma unroll
        for (int off = 16; off > 0; off >>= 1) {
            pA += __shfl_xor_sync(0xffffffffu, pA, off);
            pB += __shfl_xor_sync(0xffffffffu, pB, off);
        }

        float exA = __expf(pA) * (eA + 1e-7f);
        float exB = __expf(pB) * (eB + 1e-7f);
        denom += exA + exB;
        acc0 += exA * gA.x + exB * gB.x;
        acc1 += exA * gA.y + exB * gB.y;
        acc2 += exA * gA.z + exB * gB.z;
        acc3 += exA * gA.w + exB * gB.w;
    }
    if (j < je) {
        int src = d_src_sorted[j];
        float env = d_env_sorted[j];
        float4 gl = *reinterpret_cast<const float4*>(&d_g[src * NCAT + (lane << 2)]);
        float t0 = gl.x + gr.x, t1 = gl.y + gr.y, t2 = gl.z + gr.z, t3 = gl.w + gr.w;
        float p = (t0 * __frcp_rn(1.f + __expf(-t0))) * aw.x
                + (t1 * __frcp_rn(1.f + __expf(-t1))) * aw.y
                + (t2 * __frcp_rn(1.f + __expf(-t2))) * aw.z
                + (t3 * __frcp_rn(1.f + __expf(-t3))) * aw.w;
#pragma unroll
        for (int off = 16; off > 0; off >>= 1)
            p += __shfl_xor_sync(0xffffffffu, p, off);
        float ex = __expf(p) * (env + 1e-7f);
        denom += ex;
        acc0 += ex * gl.x;
        acc1 += ex * gl.y;
        acc2 += ex * gl.z;
        acc3 += ex * gl.w;
    }

    float inv = (denom > 0.f) ? (1.f / denom) : 0.f;
    float4 o = make_float4(acc0 * inv, acc1 * inv, acc2 * inv, acc3 * inv);
    *reinterpret_cast<float4*>(&out[n * H_CH + (lane << 2)]) = o;
}

// ---------------- launch ----------------
extern "C" void kernel_launch(void* const* d_in, const int* in_sizes, int n_in,
                              void* d_out, int out_size) {
    const float* q        = (const float*)d_in[0];
    const float* envelope = (const float*)d_in[3];
    const float* W_l      = (const float*)d_in[4];
    const float* W_r      = (const float*)d_in[5];
    const float* attn_w   = (const float*)d_in[6];
    const int*   ei       = (const int*)d_in[7];
    float* out = (float*)d_out;

    prep_kernel<<<(N_NODES + 255) / 256, 256>>>(W_l, W_r);

    dim3 ggrid((N_NODES + BM - 1) / BM, NCAT / BN);
    gemm_kernel<<<ggrid, 256>>>(q);

    hist_kernel<<<(N_EDGES / 4 + 255) / 256, 256>>>(ei);
    scan_kernel<<<1, SCAN_T>>>();
    scatter_kernel<<<(N_EDGES / 4 + 255) / 256, 256>>>(ei, envelope);

    int total_threads = N_NODES * 32;
    out_kernel<<<(total_threads + 255) / 256, 256>>>(attn_w, out);
}

// round 9
// speedup vs baseline: 1.3083x; 1.3083x over previous
#include <cuda_runtime.h>
#include <cuda_bf16.h>
#include <cstdint>

#define N_NODES 50000
#define N_EDGES 800000
#define IN_CH   128
#define H_CH    128
#define NCAT    256   // W_l and W_r stacked

// ---------------- device scratch ----------------
__device__ float d_w[NCAT * IN_CH];            // packed [W_l; W_r], row-major [256,128]
__device__ float d_g[N_NODES * NCAT];          // row n: [g_l(128) | g_r(128)]
__device__ int   d_count[N_NODES];
__device__ int   d_start[N_NODES + 1];
__device__ int   d_cursor[N_NODES];
__device__ int   d_src_sorted[N_EDGES];
__device__ float d_env_sorted[N_EDGES];
__device__ int   d_bsum[128];                  // per-block sums for multi-block scan

// ---------------- f32x2 helpers ----------------
__device__ __forceinline__ unsigned long long pack2(float lo, float hi) {
    unsigned long long r;
    asm("mov.b64 %0, {%1, %2};" : "=l"(r) : "f"(lo), "f"(hi));
    return r;
}
__device__ __forceinline__ void unpack2(unsigned long long v, float& lo, float& hi) {
    asm("mov.b64 {%0, %1}, %2;" : "=f"(lo), "=f"(hi) : "l"(v));
}
__device__ __forceinline__ unsigned long long fma2(unsigned long long a,
                                                   unsigned long long b,
                                                   unsigned long long c) {
    unsigned long long d;
    asm("fma.rn.f32x2 %0, %1, %2, %3;" : "=l"(d) : "l"(a), "l"(b), "l"(c));
    return d;
}
__device__ __forceinline__ float tanh_approx(float x) {
    float y;
    asm("tanh.approx.f32 %0, %1;" : "=f"(y) : "f"(x));
    return y;
}

// ---------------- kernel 1: pack W + zero counts (merged) ----------------
__global__ void prep_kernel(const float* __restrict__ Wl, const float* __restrict__ Wr) {
    int i = blockIdx.x * blockDim.x + threadIdx.x;
    if (i < H_CH * IN_CH) {
        d_w[i] = Wl[i];
        d_w[H_CH * IN_CH + i] = Wr[i];
    }
    if (i < N_NODES) d_count[i] = 0;
}

// ---------------- kernel 2: SGEMM via FFMA2, proven R3 tile (BM=BN=64, 4x4) ----------------
#define BM 64
#define BN 64
#define BK 16
#define PAD 68

__global__ __launch_bounds__(256) void gemm_kernel(const float* __restrict__ q) {
    __shared__ float As[BK][PAD];  // As[k][m]
    __shared__ float Bs[BK][PAD];  // Bs[k][n]

    const int block_m = blockIdx.x * BM;
    const int block_n = blockIdx.y * BN;
    const int tid = threadIdx.x;
    const int tn = tid & 15;
    const int tm = tid >> 4;

    const int lrow  = tid >> 2;
    const int lcol4 = (tid & 3) << 2;

    unsigned long long acc2[4][2];
#pragma unroll
    for (int i = 0; i < 4; i++) { acc2[i][0] = 0ULL; acc2[i][1] = 0ULL; }

#pragma unroll
    for (int k0 = 0; k0 < IN_CH; k0 += BK) {
        float4 av = make_float4(0.f, 0.f, 0.f, 0.f);
        int arow = block_m + lrow;
        if (arow < N_NODES)
            av = *reinterpret_cast<const float4*>(&q[arow * IN_CH + k0 + lcol4]);
        As[lcol4 + 0][lrow] = av.x;
        As[lcol4 + 1][lrow] = av.y;
        As[lcol4 + 2][lrow] = av.z;
        As[lcol4 + 3][lrow] = av.w;
        float4 bv = *reinterpret_cast<const float4*>(&d_w[(block_n + lrow) * IN_CH + k0 + lcol4]);
        Bs[lcol4 + 0][lrow] = bv.x;
        Bs[lcol4 + 1][lrow] = bv.y;
        Bs[lcol4 + 2][lrow] = bv.z;
        Bs[lcol4 + 3][lrow] = bv.w;
        __syncthreads();

#pragma unroll
        for (int kk = 0; kk < BK; kk++) {
            float4 a = *reinterpret_cast<const float4*>(&As[kk][tm << 2]);
            float4 b = *reinterpret_cast<const float4*>(&Bs[kk][tn << 2]);
            unsigned long long bp0 = pack2(b.x, b.y);
            unsigned long long bp1 = pack2(b.z, b.w);
            float ar[4] = {a.x, a.y, a.z, a.w};
#pragma unroll
            for (int i = 0; i < 4; i++) {
                unsigned long long ad = pack2(ar[i], ar[i]);
                acc2[i][0] = fma2(ad, bp0, acc2[i][0]);
                acc2[i][1] = fma2(ad, bp1, acc2[i][1]);
            }
        }
        __syncthreads();
    }

#pragma unroll
    for (int i = 0; i < 4; i++) {
        int row = block_m + (tm << 2) + i;
        if (row < N_NODES) {
            float o0, o1, o2, o3;
            unpack2(acc2[i][0], o0, o1);
            unpack2(acc2[i][1], o2, o3);
            *reinterpret_cast<float4*>(&d_g[row * NCAT + block_n + (tn << 2)]) =
                make_float4(o0, o1, o2, o3);
        }
    }
}

// ---------------- kernel 3: histogram of dst (4 edges/thread) ----------------
__global__ void hist_kernel(const int* __restrict__ ei) {
    int t = blockIdx.x * blockDim.x + threadIdx.x;
    int i4 = t * 4;
    if (i4 < N_EDGES) {
        int4 d = *reinterpret_cast<const int4*>(&ei[N_EDGES + i4]);
        atomicAdd(&d_count[d.x], 1);
        atomicAdd(&d_count[d.y], 1);
        atomicAdd(&d_count[d.z], 1);
        atomicAdd(&d_count[d.w], 1);
    }
}

// ---------------- multi-block scan: 3 phases ----------------
#define SCANA_T 512
#define SCAN_NBLK ((N_NODES + SCANA_T - 1) / SCANA_T)   // 98

// phase A: per-block exclusive scan (local), block totals to d_bsum
__global__ __launch_bounds__(SCANA_T) void scanA_kernel() {
    __shared__ int wt[16];
    int tid = threadIdx.x;
    int lane = tid & 31;
    int wid = tid >> 5;           // 0..15
    int idx = blockIdx.x * SCANA_T + tid;

    int v = (idx < N_NODES) ? d_count[idx] : 0;
    int ws = v;
#pragma unroll
    for (int off = 1; off < 32; off <<= 1) {
        int y = __shfl_up_sync(0xffffffffu, ws, off);
        if (lane >= off) ws += y;
    }
    if (lane == 31) wt[wid] = ws;
    __syncthreads();
    if (tid < 16) {
        int y = wt[tid];
#pragma unroll
        for (int off = 1; off < 16; off <<= 1) {
            int z = __shfl_up_sync(0x0000ffffu, y, off);
            if (tid >= off) y += z;
        }
        wt[tid] = y;
    }
    __syncthreads();
    int incl = ws + (wid ? wt[wid - 1] : 0);
    if (idx < N_NODES) d_start[idx] = incl - v;   // block-local exclusive
    if (tid == SCANA_T - 1) d_bsum[blockIdx.x] = incl;
}

// phase B: scan the 98 block sums (1 block, 128 threads), write total
__global__ __launch_bounds__(128) void scanB_kernel() {
    __shared__ int wt[4];
    int tid = threadIdx.x;
    int lane = tid & 31;
    int wid = tid >> 5;     // 0..3
    int v = (tid < SCAN_NBLK) ? d_bsum[tid] : 0;
    int ws = v;
#pragma unroll
    for (int off = 1; off < 32; off <<= 1) {
        int y = __shfl_up_sync(0xffffffffu, ws, off);
        if (lane >= off) ws += y;
    }
    if (lane == 31) wt[wid] = ws;
    __syncthreads();
    if (tid < 4) {
        int y = wt[tid];
#pragma unroll
        for (int off = 1; off < 4; off <<= 1) {
            int z = __shfl_up_sync(0x0000000fu, y, off);
            if (tid >= off) y += z;
        }
        wt[tid] = y;
    }
    __syncthreads();
    int incl = ws + (wid ? wt[wid - 1] : 0);
    if (tid < SCAN_NBLK) d_bsum[tid] = incl - v;  // exclusive block offsets
    if (tid == 127) d_start[N_NODES] = incl;      // grand total (= N_EDGES)
}

// phase C: add block offsets, fill cursor
__global__ __launch_bounds__(SCANA_T) void scanC_kernel() {
    int idx = blockIdx.x * SCANA_T + threadIdx.x;
    if (idx < N_NODES) {
        int e = d_start[idx] + d_bsum[blockIdx.x];
        d_start[idx]  = e;
        d_cursor[idx] = e;
    }
}

// ---------------- kernel 5: scatter edges (4 edges/thread, bounds-guarded) ----------------
__global__ void scatter_kernel(const int* __restrict__ ei,
                               const float* __restrict__ envelope) {
    int t = blockIdx.x * blockDim.x + threadIdx.x;
    int i4 = t * 4;
    if (i4 < N_EDGES) {
        int4   s = *reinterpret_cast<const int4*>(&ei[i4]);
        int4   d = *reinterpret_cast<const int4*>(&ei[N_EDGES + i4]);
        float4 e = *reinterpret_cast<const float4*>(&envelope[i4]);
        int p0 = atomicAdd(&d_cursor[d.x], 1);
        if ((unsigned)p0 < N_EDGES) { d_src_sorted[p0] = s.x; d_env_sorted[p0] = e.x; }
        int p1 = atomicAdd(&d_cursor[d.y], 1);
        if ((unsigned)p1 < N_EDGES) { d_src_sorted[p1] = s.y; d_env_sorted[p1] = e.y; }
        int p2 = atomicAdd(&d_cursor[d.z], 1);
        if ((unsigned)p2 < N_EDGES) { d_src_sorted[p2] = s.z; d_env_sorted[p2] = e.z; }
        int p3 = atomicAdd(&d_cursor[d.w], 1);
        if ((unsigned)p3 < N_EDGES) { d_src_sorted[p3] = s.w; d_env_sorted[p3] = e.w; }
    }
}

// ---------------- kernel 6: per-node softmax + aggregation ----------------
// silu via tanh: sigmoid(t) = 0.5 + 0.5*tanh(0.5*t)  -> 1 MUFU per channel
__device__ __forceinline__ float silu_t(float t) {
    float th = tanh_approx(0.5f * t);
    return t * fmaf(0.5f, th, 0.5f);
}

__global__ __launch_bounds__(256) void out_kernel(const float* __restrict__ attn_w,
                                                  float* __restrict__ out) {
    int warp_id = (blockIdx.x * blockDim.x + threadIdx.x) >> 5;
    if (warp_id >= N_NODES) return;
    int lane = threadIdx.x & 31;
    int n = warp_id;

    float4 gr = *reinterpret_cast<const float4*>(&d_g[n * NCAT + H_CH + (lane << 2)]);
    float4 aw = *reinterpret_cast<const float4*>(&attn_w[lane << 2]);

    float acc0 = 0.f, acc1 = 0.f, acc2 = 0.f, acc3 = 0.f;
    float denom = 0.f;

    int js = d_start[n];
    int je = d_start[n + 1];
    js = (js < 0) ? 0 : js;
    je = (je > N_EDGES) ? N_EDGES : je;
    int j = js;

    for (; j + 1 < je; j += 2) {
        int sA = d_src_sorted[j];
        int sB = d_src_sorted[j + 1];
        float eA = d_env_sorted[j];
        float eB = d_env_sorted[j + 1];
        float4 gA = *reinterpret_cast<const float4*>(&d_g[sA * NCAT + (lane << 2)]);
        float4 gB = *reinterpret_cast<const float4*>(&d_g[sB * NCAT + (lane << 2)]);

        float pA = silu_t(gA.x + gr.x) * aw.x + silu_t(gA.y + gr.y) * aw.y
                 + silu_t(gA.z + gr.z) * aw.z + silu_t(gA.w + gr.w) * aw.w;
        float pB = silu_t(gB.x + gr.x) * aw.x + silu_t(gB.y + gr.y) * aw.y
                 + silu_t(gB.z + gr.z) * aw.z + silu_t(gB.w + gr.w) * aw.w;

#pragma unroll
        for (int off = 16; off > 0; off >>= 1) {
            pA += __shfl_xor_sync(0xffffffffu, pA, off);
            pB += __shfl_xor_sync(0xffffffffu, pB, off);
        }

        float exA = __expf(pA) * (eA + 1e-7f);
        float exB = __expf(pB) * (eB + 1e-7f);
        denom += exA + exB;
        acc0 += exA * gA.x + exB * gB.x;
        acc1 += exA * gA.y + exB * gB.y;
        acc2 += exA * gA.z + exB * gB.z;
        acc3 += exA * gA.w + exB * gB.w;
    }
    if (j < je) {
        int src = d_src_sorted[j];
        float env = d_env_sorted[j];
        float4 gl = *reinterpret_cast<const float4*>(&d_g[src * NCAT + (lane << 2)]);
        float p = silu_t(gl.x + gr.x) * aw.x + silu_t(gl.y + gr.y) * aw.y
                + silu_t(gl.z + gr.z) * aw.z + silu_t(gl.w + gr.w) * aw.w;
#pragma unroll
        for (int off = 16; off > 0; off >>= 1)
            p += __shfl_xor_sync(0xffffffffu, p, off);
        float ex = __expf(p) * (env + 1e-7f);
        denom += ex;
        acc0 += ex * gl.x;
        acc1 += ex * gl.y;
        acc2 += ex * gl.z;
        acc3 += ex * gl.w;
    }

    float inv = (denom > 0.f) ? (1.f / denom) : 0.f;
    float4 o = make_float4(acc0 * inv, acc1 * inv, acc2 * inv, acc3 * inv);
    *reinterpret_cast<float4*>(&out[n * H_CH + (lane << 2)]) = o;
}

// ---------------- launch ----------------
extern "C" void kernel_launch(void* const* d_in, const int* in_sizes, int n_in,
                              void* d_out, int out_size) {
    const float* q        = (const float*)d_in[0];
    const float* envelope = (const float*)d_in[3];
    const float* W_l      = (const float*)d_in[4];
    const float* W_r      = (const float*)d_in[5];
    const float* attn_w   = (const float*)d_in[6];
    const int*   ei       = (const int*)d_in[7];
    float* out = (float*)d_out;

    prep_kernel<<<(N_NODES + 255) / 256, 256>>>(W_l, W_r);

    dim3 ggrid((N_NODES + BM - 1) / BM, NCAT / BN);
    gemm_kernel<<<ggrid, 256>>>(q);

    hist_kernel<<<(N_EDGES / 4 + 255) / 256, 256>>>(ei);
    scanA_kernel<<<SCAN_NBLK, SCANA_T>>>();
    scanB_kernel<<<1, 128>>>();
    scanC_kernel<<<SCAN_NBLK, SCANA_T>>>();
    scatter_kernel<<<(N_EDGES / 4 + 255) / 256, 256>>>(ei, envelope);

    int total_threads = N_NODES * 32;
    out_kernel<<<(total_threads + 255) / 256, 256>>>(attn_w, out);
}